// round 10
// baseline (speedup 1.0000x reference)
#include <cuda_runtime.h>
#include <cuda_bf16.h>
#include <math_constants.h>
#include <cstdint>

// Problem constants (reference: N=100000, E=1200000, all dims 128)
#define MAXN 100000
#define MAXE 1200000
#define MAXE2 (MAXE + MAXN)

// Scratch (device globals — allocation-free rule)
__device__ __align__(16) float g_xw[MAXN * 128];     // x @ W            [N,128]
__device__ __align__(16) float g_h[MAXN * 128];      // layer output     [N,128]
__device__ __align__(16) float g_ssrc[MAXN * 4];
__device__ __align__(16) float g_sdst[MAXN * 4];

__device__ int g_counts[MAXN];
__device__ int g_cursor[MAXN];
__device__ int g_rowptr[MAXN + 1];
__device__ int g_csr[MAXE2];                          // src per CSR slot (dst-sorted)

// ---------------------------------------------------------------------------
// GEMM: g_xw[n,128] = A[n,128] @ W[128,128], with fused attention-score
// epilogue (g_ssrc/g_sdst). Block: 256 threads, tile 64 rows x 128 cols.
// ---------------------------------------------------------------------------
__global__ __launch_bounds__(256) void gemm128_k(
    const float* __restrict__ A, const float* __restrict__ W,
    const float* __restrict__ as_, const float* __restrict__ ad_, int n)
{
    extern __shared__ float sm[];
    float4* sA4 = (float4*)sm;               // 64 x 32 float4
    float4* sW4 = (float4*)(sm + 64 * 128);  // 128 x 32 float4

    int t = threadIdx.x;
    int row0 = blockIdx.x * 64;

    const float4* A4 = (const float4*)A;
    #pragma unroll
    for (int i = 0; i < 8; i++) {
        int idx = t + i * 256;
        int r = idx >> 5, c = idx & 31;
        float4 v = make_float4(0.f, 0.f, 0.f, 0.f);
        if (row0 + r < n) v = A4[(size_t)(row0 + r) * 32 + c];
        sA4[idx] = v;
    }
    const float4* W4 = (const float4*)W;
    #pragma unroll
    for (int i = 0; i < 16; i++) {
        int idx = t + i * 256;
        sW4[idx] = W4[idx];
    }
    __syncthreads();

    int tx = t & 31, ty = t >> 5;            // tx: col-group (4 cols), ty: warp
    float4 acc[8];
    #pragma unroll
    for (int i = 0; i < 8; i++) acc[i] = make_float4(0.f, 0.f, 0.f, 0.f);

    #pragma unroll
    for (int k4 = 0; k4 < 32; k4++) {
        float4 w0 = sW4[(4 * k4 + 0) * 32 + tx];
        float4 w1 = sW4[(4 * k4 + 1) * 32 + tx];
        float4 w2 = sW4[(4 * k4 + 2) * 32 + tx];
        float4 w3 = sW4[(4 * k4 + 3) * 32 + tx];
        #pragma unroll
        for (int i = 0; i < 8; i++) {
            float4 a = sA4[(i * 8 + ty) * 32 + k4];
            acc[i].x = fmaf(a.x, w0.x, fmaf(a.y, w1.x, fmaf(a.z, w2.x, fmaf(a.w, w3.x, acc[i].x))));
            acc[i].y = fmaf(a.x, w0.y, fmaf(a.y, w1.y, fmaf(a.z, w2.y, fmaf(a.w, w3.y, acc[i].y))));
            acc[i].z = fmaf(a.x, w0.z, fmaf(a.y, w1.z, fmaf(a.z, w2.z, fmaf(a.w, w3.z, acc[i].z))));
            acc[i].w = fmaf(a.x, w0.w, fmaf(a.y, w1.w, fmaf(a.z, w2.w, fmaf(a.w, w3.w, acc[i].w))));
        }
    }

    // Write xw
    float4* O4 = (float4*)g_xw;
    #pragma unroll
    for (int i = 0; i < 8; i++) {
        int r = row0 + i * 8 + ty;
        if (r < n) O4[(size_t)r * 32 + tx] = acc[i];
    }

    // Fused score epilogue: cols 4tx..4tx+3 all belong to head tx>>3.
    float4 av = __ldg((const float4*)as_ + tx);
    float4 dv = __ldg((const float4*)ad_ + tx);
    int head = tx >> 3;
    #pragma unroll
    for (int i = 0; i < 8; i++) {
        float ps = acc[i].x * av.x + acc[i].y * av.y + acc[i].z * av.z + acc[i].w * av.w;
        float pd = acc[i].x * dv.x + acc[i].y * dv.y + acc[i].z * dv.z + acc[i].w * dv.w;
        ps += __shfl_xor_sync(0xffffffffu, ps, 1);
        ps += __shfl_xor_sync(0xffffffffu, ps, 2);
        ps += __shfl_xor_sync(0xffffffffu, ps, 4);
        pd += __shfl_xor_sync(0xffffffffu, pd, 1);
        pd += __shfl_xor_sync(0xffffffffu, pd, 2);
        pd += __shfl_xor_sync(0xffffffffu, pd, 4);
        int r = row0 + i * 8 + ty;
        if ((tx & 7) == 0 && r < n) {
            g_ssrc[(size_t)r * 4 + head] = ps;
            g_sdst[(size_t)r * 4 + head] = pd;
        }
    }
}

// ---------------------------------------------------------------------------
// CSR build (once; edge structure identical across layers)
// ---------------------------------------------------------------------------
__global__ void hist_k(const int* __restrict__ ei, int E, int E2)
{
    int e = blockIdx.x * blockDim.x + threadIdx.x;
    if (e >= E2) return;
    int d = (e < E) ? __ldg(ei + E + e) : (e - E);
    atomicAdd(g_counts + d, 1);
}

__global__ __launch_bounds__(1024) void scan_k(int n, int E2)
{
    __shared__ int warpsums[32];
    __shared__ int s_carry;
    int lane = threadIdx.x & 31, wid = threadIdx.x >> 5;
    if (threadIdx.x == 0) s_carry = 0;
    __syncthreads();

    for (int base = 0; base < n; base += 1024) {
        int i = base + threadIdx.x;
        int v = (i < n) ? g_counts[i] : 0;
        int x = v;
        #pragma unroll
        for (int off = 1; off < 32; off <<= 1) {
            int t = __shfl_up_sync(0xffffffffu, x, off);
            if (lane >= off) x += t;
        }
        if (lane == 31) warpsums[wid] = x;
        __syncthreads();
        if (wid == 0) {
            int ws = warpsums[lane];
            #pragma unroll
            for (int off = 1; off < 32; off <<= 1) {
                int t = __shfl_up_sync(0xffffffffu, ws, off);
                if (lane >= off) ws += t;
            }
            warpsums[lane] = ws;
        }
        __syncthreads();
        int incl = x + (wid > 0 ? warpsums[wid - 1] : 0);
        int carry = s_carry;
        if (i < n) {
            g_rowptr[i + 1] = carry + incl;
            g_cursor[i] = carry + incl - v;
        }
        __syncthreads();
        if (threadIdx.x == 1023) s_carry = carry + warpsums[31];
        __syncthreads();
    }
    if (threadIdx.x == 0) { g_rowptr[0] = 0; g_rowptr[n] = E2; }
}

__global__ void scatter_k(const int* __restrict__ ei, int E, int E2)
{
    int e = blockIdx.x * blockDim.x + threadIdx.x;
    if (e >= E2) return;
    int s, d;
    if (e < E) { s = __ldg(ei + e); d = __ldg(ei + E + e); }
    else       { s = d = e - E; }
    int pos = atomicAdd(g_cursor + d, 1);
    g_csr[pos] = s;
}

// ---------------------------------------------------------------------------
// Single-pass fused softmax + aggregation. One warp per destination node.
// out = (sum_j ex_j * xw[src_j]) / (sum_j ex_j); no max shift (scores O(1)),
// no alpha scratch. All lanes compute ex redundantly (same MUFU warp-slots).
// mode 0: out = elu(agg + bias) [N,128];  mode 1: out = mean_heads(agg)+b [N,32]
// ---------------------------------------------------------------------------
__global__ __launch_bounds__(256) void fused_gat_k(
    const float* __restrict__ bias, float* __restrict__ out, int n, int mode)
{
    int gid = blockIdx.x * blockDim.x + threadIdx.x;
    int node = gid >> 5, lane = gid & 31;
    if (node >= n) return;

    int beg = g_rowptr[node];
    int end = g_rowptr[node + 1];
    int h = lane >> 3;

    float sd_h = g_sdst[(size_t)node * 4 + h];

    float den = 0.f;
    float4 acc = make_float4(0.f, 0.f, 0.f, 0.f);

    #pragma unroll 2
    for (int j = beg; j < end; j++) {
        int s = g_csr[j];                                  // warp-uniform
        float a = g_ssrc[(size_t)s * 4 + h] + sd_h;        // 8-way broadcast
        a = a > 0.f ? a : 0.2f * a;
        float ex = __expf(a);
        den += ex;
        float4 v = *(const float4*)(g_xw + (size_t)s * 128 + lane * 4);
        acc.x = fmaf(v.x, ex, acc.x);
        acc.y = fmaf(v.y, ex, acc.y);
        acc.z = fmaf(v.z, ex, acc.z);
        acc.w = fmaf(v.w, ex, acc.w);
    }

    float inv = 1.0f / fmaxf(den, 1e-16f);
    acc.x *= inv; acc.y *= inv; acc.z *= inv; acc.w *= inv;

    if (mode == 0) {
        float4 b = *(const float4*)(bias + lane * 4);
        float4 o;
        o.x = acc.x + b.x; o.x = o.x > 0.f ? o.x : (expf(o.x) - 1.f);
        o.y = acc.y + b.y; o.y = o.y > 0.f ? o.y : (expf(o.y) - 1.f);
        o.z = acc.z + b.z; o.z = o.z > 0.f ? o.z : (expf(o.z) - 1.f);
        o.w = acc.w + b.w; o.w = o.w > 0.f ? o.w : (expf(o.w) - 1.f);
        *(float4*)(out + (size_t)node * 128 + lane * 4) = o;
    } else {
        // mean over 4 heads: lanes {l, l^8, l^16, l^24} hold same feature group
        acc.x += __shfl_xor_sync(0xffffffffu, acc.x, 8);
        acc.y += __shfl_xor_sync(0xffffffffu, acc.y, 8);
        acc.z += __shfl_xor_sync(0xffffffffu, acc.z, 8);
        acc.w += __shfl_xor_sync(0xffffffffu, acc.w, 8);
        acc.x += __shfl_xor_sync(0xffffffffu, acc.x, 16);
        acc.y += __shfl_xor_sync(0xffffffffu, acc.y, 16);
        acc.z += __shfl_xor_sync(0xffffffffu, acc.z, 16);
        acc.w += __shfl_xor_sync(0xffffffffu, acc.w, 16);
        if (lane < 8) {
            float4 b = *(const float4*)(bias + lane * 4);
            float4 o;
            o.x = 0.25f * acc.x + b.x;
            o.y = 0.25f * acc.y + b.y;
            o.z = 0.25f * acc.z + b.z;
            o.w = 0.25f * acc.w + b.w;
            *(float4*)(out + (size_t)node * 32 + lane * 4) = o;
        }
    }
}

// ---------------------------------------------------------------------------
extern "C" void kernel_launch(void* const* d_in, const int* in_sizes, int n_in,
                              void* d_out, int out_size)
{
    const float* x  = (const float*)d_in[0];
    const int*   ei = (const int*)d_in[1];
    const float* W[3]  = {(const float*)d_in[2], (const float*)d_in[6],  (const float*)d_in[10]};
    const float* AS[3] = {(const float*)d_in[3], (const float*)d_in[7],  (const float*)d_in[11]};
    const float* AD[3] = {(const float*)d_in[4], (const float*)d_in[8],  (const float*)d_in[12]};
    const float* B[3]  = {(const float*)d_in[5], (const float*)d_in[9],  (const float*)d_in[13]};

    int n  = in_sizes[0] / 128;
    int E  = in_sizes[1] / 2;
    int E2 = E + n;

    float* hbuf = nullptr;
    cudaGetSymbolAddress((void**)&hbuf, g_h);
    int* counts_ptr = nullptr;
    cudaGetSymbolAddress((void**)&counts_ptr, g_counts);

    const int SMEM = (64 * 128 + 128 * 128) * (int)sizeof(float);  // 96 KB
    cudaFuncSetAttribute(gemm128_k, cudaFuncAttributeMaxDynamicSharedMemorySize, SMEM);

    // CSR build (edge structure shared by all 3 layers)
    cudaMemsetAsync(counts_ptr, 0, (size_t)n * sizeof(int));
    hist_k<<<(E2 + 255) / 256, 256>>>(ei, E, E2);
    scan_k<<<1, 1024>>>(n, E2);
    scatter_k<<<(E2 + 255) / 256, 256>>>(ei, E, E2);

    const float* in = x;
    for (int L = 0; L < 3; L++) {
        gemm128_k<<<(n + 63) / 64, 256, SMEM>>>(in, W[L], AS[L], AD[L], n);
        if (L < 2) {
            fused_gat_k<<<(n * 32 + 255) / 256, 256>>>(B[L], hbuf, n, 0);
            in = hbuf;
        } else {
            fused_gat_k<<<(n * 32 + 255) / 256, 256>>>(B[2], (float*)d_out, n, 1);
        }
    }
}

// round 11
// speedup vs baseline: 1.5159x; 1.5159x over previous
#include <cuda_runtime.h>
#include <cuda_bf16.h>
#include <math_constants.h>
#include <cstdint>

// Problem constants (reference: N=100000, E=1200000, all dims 128)
#define MAXN 100000
#define MAXE 1200000
#define MAXE2 (MAXE + MAXN)

// Scratch (device globals — allocation-free rule)
__device__ __align__(16) float g_xw[MAXN * 128];     // x @ W            [N,128]
__device__ __align__(16) float g_h[MAXN * 128];      // layer output     [N,128]
__device__ __align__(16) float g_ssrc[MAXN * 4];
__device__ __align__(16) float g_sdst[MAXN * 4];

__device__ int g_counts[MAXN];
__device__ int g_cursor[MAXN];
__device__ int g_rowptr[MAXN + 1];
__device__ int g_csr[MAXE2];                          // src per CSR slot (dst-sorted)

// ---------------------------------------------------------------------------
// GEMM: g_xw[n,128] = A[n,128] @ W[128,128], with fused attention-score
// epilogue (g_ssrc/g_sdst). Block: 256 threads, tile 64 rows x 128 cols.
// ---------------------------------------------------------------------------
__global__ __launch_bounds__(256) void gemm128_k(
    const float* __restrict__ A, const float* __restrict__ W,
    const float* __restrict__ as_, const float* __restrict__ ad_, int n)
{
    extern __shared__ float sm[];
    float4* sA4 = (float4*)sm;               // 64 x 32 float4
    float4* sW4 = (float4*)(sm + 64 * 128);  // 128 x 32 float4

    int t = threadIdx.x;
    int row0 = blockIdx.x * 64;

    const float4* A4 = (const float4*)A;
    #pragma unroll
    for (int i = 0; i < 8; i++) {
        int idx = t + i * 256;
        int r = idx >> 5, c = idx & 31;
        float4 v = make_float4(0.f, 0.f, 0.f, 0.f);
        if (row0 + r < n) v = A4[(size_t)(row0 + r) * 32 + c];
        sA4[idx] = v;
    }
    const float4* W4 = (const float4*)W;
    #pragma unroll
    for (int i = 0; i < 16; i++) {
        int idx = t + i * 256;
        sW4[idx] = W4[idx];
    }
    __syncthreads();

    int tx = t & 31, ty = t >> 5;            // tx: col-group (4 cols), ty: warp
    float4 acc[8];
    #pragma unroll
    for (int i = 0; i < 8; i++) acc[i] = make_float4(0.f, 0.f, 0.f, 0.f);

    #pragma unroll
    for (int k4 = 0; k4 < 32; k4++) {
        float4 w0 = sW4[(4 * k4 + 0) * 32 + tx];
        float4 w1 = sW4[(4 * k4 + 1) * 32 + tx];
        float4 w2 = sW4[(4 * k4 + 2) * 32 + tx];
        float4 w3 = sW4[(4 * k4 + 3) * 32 + tx];
        #pragma unroll
        for (int i = 0; i < 8; i++) {
            float4 a = sA4[(i * 8 + ty) * 32 + k4];
            acc[i].x = fmaf(a.x, w0.x, fmaf(a.y, w1.x, fmaf(a.z, w2.x, fmaf(a.w, w3.x, acc[i].x))));
            acc[i].y = fmaf(a.x, w0.y, fmaf(a.y, w1.y, fmaf(a.z, w2.y, fmaf(a.w, w3.y, acc[i].y))));
            acc[i].z = fmaf(a.x, w0.z, fmaf(a.y, w1.z, fmaf(a.z, w2.z, fmaf(a.w, w3.z, acc[i].z))));
            acc[i].w = fmaf(a.x, w0.w, fmaf(a.y, w1.w, fmaf(a.z, w2.w, fmaf(a.w, w3.w, acc[i].w))));
        }
    }

    // Write xw
    float4* O4 = (float4*)g_xw;
    #pragma unroll
    for (int i = 0; i < 8; i++) {
        int r = row0 + i * 8 + ty;
        if (r < n) O4[(size_t)r * 32 + tx] = acc[i];
    }

    // Fused score epilogue: cols 4tx..4tx+3 all belong to head tx>>3.
    float4 av = __ldg((const float4*)as_ + tx);
    float4 dv = __ldg((const float4*)ad_ + tx);
    int head = tx >> 3;
    #pragma unroll
    for (int i = 0; i < 8; i++) {
        float ps = acc[i].x * av.x + acc[i].y * av.y + acc[i].z * av.z + acc[i].w * av.w;
        float pd = acc[i].x * dv.x + acc[i].y * dv.y + acc[i].z * dv.z + acc[i].w * dv.w;
        ps += __shfl_xor_sync(0xffffffffu, ps, 1);
        ps += __shfl_xor_sync(0xffffffffu, ps, 2);
        ps += __shfl_xor_sync(0xffffffffu, ps, 4);
        pd += __shfl_xor_sync(0xffffffffu, pd, 1);
        pd += __shfl_xor_sync(0xffffffffu, pd, 2);
        pd += __shfl_xor_sync(0xffffffffu, pd, 4);
        int r = row0 + i * 8 + ty;
        if ((tx & 7) == 0 && r < n) {
            g_ssrc[(size_t)r * 4 + head] = ps;
            g_sdst[(size_t)r * 4 + head] = pd;
        }
    }
}

// ---------------------------------------------------------------------------
// CSR build (once; edge structure identical across layers)
// ---------------------------------------------------------------------------
__global__ void hist_k(const int* __restrict__ ei, int E, int E2)
{
    int e = blockIdx.x * blockDim.x + threadIdx.x;
    if (e >= E2) return;
    int d = (e < E) ? __ldg(ei + E + e) : (e - E);
    atomicAdd(g_counts + d, 1);
}

__global__ __launch_bounds__(1024) void scan_k(int n, int E2)
{
    __shared__ int warpsums[32];
    __shared__ int s_carry;
    int lane = threadIdx.x & 31, wid = threadIdx.x >> 5;
    if (threadIdx.x == 0) s_carry = 0;
    __syncthreads();

    for (int base = 0; base < n; base += 1024) {
        int i = base + threadIdx.x;
        int v = (i < n) ? g_counts[i] : 0;
        int x = v;
        #pragma unroll
        for (int off = 1; off < 32; off <<= 1) {
            int t = __shfl_up_sync(0xffffffffu, x, off);
            if (lane >= off) x += t;
        }
        if (lane == 31) warpsums[wid] = x;
        __syncthreads();
        if (wid == 0) {
            int ws = warpsums[lane];
            #pragma unroll
            for (int off = 1; off < 32; off <<= 1) {
                int t = __shfl_up_sync(0xffffffffu, ws, off);
                if (lane >= off) ws += t;
            }
            warpsums[lane] = ws;
        }
        __syncthreads();
        int incl = x + (wid > 0 ? warpsums[wid - 1] : 0);
        int carry = s_carry;
        if (i < n) {
            g_rowptr[i + 1] = carry + incl;
            g_cursor[i] = carry + incl - v;
        }
        __syncthreads();
        if (threadIdx.x == 1023) s_carry = carry + warpsums[31];
        __syncthreads();
    }
    if (threadIdx.x == 0) { g_rowptr[0] = 0; g_rowptr[n] = E2; }
}

__global__ void scatter_k(const int* __restrict__ ei, int E, int E2)
{
    int e = blockIdx.x * blockDim.x + threadIdx.x;
    if (e >= E2) return;
    int s, d;
    if (e < E) { s = __ldg(ei + e); d = __ldg(ei + E + e); }
    else       { s = d = e - E; }
    int pos = atomicAdd(g_cursor + d, 1);
    g_csr[pos] = s;
}

// ---------------------------------------------------------------------------
// Single-pass fused softmax + aggregation. One warp per destination node.
// out = (sum_j ex_j * xw[src_j]) / (sum_j ex_j); no max shift (scores O(1)),
// no alpha scratch. All lanes compute ex redundantly (same MUFU warp-slots).
// mode 0: out = elu(agg + bias) [N,128];  mode 1: out = mean_heads(agg)+b [N,32]
// ---------------------------------------------------------------------------
__global__ __launch_bounds__(256) void fused_gat_k(
    const float* __restrict__ bias, float* __restrict__ out, int n, int mode)
{
    int gid = blockIdx.x * blockDim.x + threadIdx.x;
    int node = gid >> 5, lane = gid & 31;
    if (node >= n) return;

    int beg = g_rowptr[node];
    int end = g_rowptr[node + 1];
    int h = lane >> 3;

    float sd_h = g_sdst[(size_t)node * 4 + h];

    float den = 0.f;
    float4 acc = make_float4(0.f, 0.f, 0.f, 0.f);

    #pragma unroll 2
    for (int j = beg; j < end; j++) {
        int s = g_csr[j];                                  // warp-uniform
        float a = g_ssrc[(size_t)s * 4 + h] + sd_h;        // 8-way broadcast
        a = a > 0.f ? a : 0.2f * a;
        float ex = __expf(a);
        den += ex;
        float4 v = *(const float4*)(g_xw + (size_t)s * 128 + lane * 4);
        acc.x = fmaf(v.x, ex, acc.x);
        acc.y = fmaf(v.y, ex, acc.y);
        acc.z = fmaf(v.z, ex, acc.z);
        acc.w = fmaf(v.w, ex, acc.w);
    }

    float inv = 1.0f / fmaxf(den, 1e-16f);
    acc.x *= inv; acc.y *= inv; acc.z *= inv; acc.w *= inv;

    if (mode == 0) {
        float4 b = *(const float4*)(bias + lane * 4);
        float4 o;
        o.x = acc.x + b.x; o.x = o.x > 0.f ? o.x : (expf(o.x) - 1.f);
        o.y = acc.y + b.y; o.y = o.y > 0.f ? o.y : (expf(o.y) - 1.f);
        o.z = acc.z + b.z; o.z = o.z > 0.f ? o.z : (expf(o.z) - 1.f);
        o.w = acc.w + b.w; o.w = o.w > 0.f ? o.w : (expf(o.w) - 1.f);
        *(float4*)(out + (size_t)node * 128 + lane * 4) = o;
    } else {
        // mean over 4 heads: lanes {l, l^8, l^16, l^24} hold same feature group
        acc.x += __shfl_xor_sync(0xffffffffu, acc.x, 8);
        acc.y += __shfl_xor_sync(0xffffffffu, acc.y, 8);
        acc.z += __shfl_xor_sync(0xffffffffu, acc.z, 8);
        acc.w += __shfl_xor_sync(0xffffffffu, acc.w, 8);
        acc.x += __shfl_xor_sync(0xffffffffu, acc.x, 16);
        acc.y += __shfl_xor_sync(0xffffffffu, acc.y, 16);
        acc.z += __shfl_xor_sync(0xffffffffu, acc.z, 16);
        acc.w += __shfl_xor_sync(0xffffffffu, acc.w, 16);
        if (lane < 8) {
            float4 b = *(const float4*)(bias + lane * 4);
            float4 o;
            o.x = 0.25f * acc.x + b.x;
            o.y = 0.25f * acc.y + b.y;
            o.z = 0.25f * acc.z + b.z;
            o.w = 0.25f * acc.w + b.w;
            *(float4*)(out + (size_t)node * 32 + lane * 4) = o;
        }
    }
}

// ---------------------------------------------------------------------------
extern "C" void kernel_launch(void* const* d_in, const int* in_sizes, int n_in,
                              void* d_out, int out_size)
{
    const float* x  = (const float*)d_in[0];
    const int*   ei = (const int*)d_in[1];
    const float* W[3]  = {(const float*)d_in[2], (const float*)d_in[6],  (const float*)d_in[10]};
    const float* AS[3] = {(const float*)d_in[3], (const float*)d_in[7],  (const float*)d_in[11]};
    const float* AD[3] = {(const float*)d_in[4], (const float*)d_in[8],  (const float*)d_in[12]};
    const float* B[3]  = {(const float*)d_in[5], (const float*)d_in[9],  (const float*)d_in[13]};

    int n  = in_sizes[0] / 128;
    int E  = in_sizes[1] / 2;
    int E2 = E + n;

    float* hbuf = nullptr;
    cudaGetSymbolAddress((void**)&hbuf, g_h);
    int* counts_ptr = nullptr;
    cudaGetSymbolAddress((void**)&counts_ptr, g_counts);

    const int SMEM = (64 * 128 + 128 * 128) * (int)sizeof(float);  // 96 KB
    cudaFuncSetAttribute(gemm128_k, cudaFuncAttributeMaxDynamicSharedMemorySize, SMEM);

    // CSR build (edge structure shared by all 3 layers)
    cudaMemsetAsync(counts_ptr, 0, (size_t)n * sizeof(int));
    hist_k<<<(E2 + 255) / 256, 256>>>(ei, E, E2);
    scan_k<<<1, 1024>>>(n, E2);
    scatter_k<<<(E2 + 255) / 256, 256>>>(ei, E, E2);

    const float* in = x;
    for (int L = 0; L < 3; L++) {
        gemm128_k<<<(n + 63) / 64, 256, SMEM>>>(in, W[L], AS[L], AD[L], n);
        if (L < 2) {
            fused_gat_k<<<(n * 32 + 255) / 256, 256>>>(B[L], hbuf, n, 0);
            in = hbuf;
        } else {
            fused_gat_k<<<(n * 32 + 255) / 256, 256>>>(B[2], (float*)d_out, n, 1);
        }
    }
}